// round 2
// baseline (speedup 1.0000x reference)
#include <cuda_runtime.h>
#include <math.h>

#define T_LEN   1000000
#define S_LEN    999999     // number of RK4 steps (T-1)
#define L_CH     27         // steps per chunk
#define NBLK     148
#define BLK      256
#define C1       (NBLK*BLK) // 37888 chunks
#define GRP      37         // chunks per group
#define C2       1024       // groups (GRP*C2 == C1)

// ---------------- scratch (__device__ globals; no allocations) ----------------
__device__ float4 g_F [C1*3];
__device__ float4 g_G [C1*3];
__device__ float4 g_H [C2*3];
__device__ float4 g_P0[C2*3];
__device__ float4 g_P1[C2*3];
__device__ float4 g_Pf[C2*3];

__device__ float g_Mcol[144];     // column-major fp32
__device__ float g_MLcol[144];    // M^27 column-major
__device__ float g_Wcol[10*144];  // (M^999)^(2^k), k=0..9, column-major
__device__ float g_ptv[12], g_qtv[12], g_vv[12];

// fp64 setup scratch
__device__ double dA_[144], dA2_[144], dA3_[144], dA4_[144];
__device__ double dM_[144], dP2_[144], dP4_[144], dP8_[144], dP16_[144];
__device__ double dT1_[144], dT2_[144], dML_[144];
__device__ double dW_[10][144];

// 12x12 fp64 matmul, one element per thread (t<144), block-synchronized
__device__ __forceinline__ void mm144(double* dst, const double* a, const double* b, int t) {
    double s = 0.0;
    if (t < 144) {
        int r = t / 12, c = t % 12;
        #pragma unroll
        for (int k = 0; k < 12; k++) s += a[r*12+k] * b[k*12+c];
    }
    if (t < 144) dst[t] = s;
    __syncthreads();
}

// ---------------- K0: setup (fp64 -> fp32) ----------------
__global__ void k_setup(const float* __restrict__ t_eval, const float* __restrict__ A,
                        const float* __restrict__ B, const float* __restrict__ loads_raw,
                        const float* __restrict__ room_areas) {
    __shared__ double sQw[10], sb0[12], sBq[12];
    __shared__ double sh;
    int t = threadIdx.x;

    if (t == 0) sh = (double)t_eval[1] - (double)t_eval[0];
    if (t < 10) {
        double x = (double)loads_raw[10 + t];               // gain_load row (action=0)
        sQw[t] = 1.0 / (1.0 + exp(-x)) * 50.0 * (double)room_areas[t];
    }
    if (t < 144) dA_[t] = (double)A[t];
    __syncthreads();

    if (t < 12) {
        sb0[t] = (double)B[t*11];
        double s = 0.0;
        #pragma unroll
        for (int j = 0; j < 10; j++) s += (double)B[t*11 + 1 + j] * sQw[j];
        sBq[t] = s;
    }
    __syncthreads();

    mm144(dA2_, dA_,  dA_, t);
    mm144(dA3_, dA2_, dA_, t);
    mm144(dA4_, dA3_, dA_, t);

    double h = sh, h2 = h*h, h3 = h2*h, h4 = h3*h;
    if (t < 144) {
        int r = t / 12, c = t % 12;
        dM_[t] = (r == c ? 1.0 : 0.0) + h*dA_[t] + h2/2.0*dA2_[t] + h3/6.0*dA3_[t] + h4/24.0*dA4_[t];
    }
    if (t < 12) {
        int r = t;
        double ab0=0,a2b0=0,a3b0=0,abq=0,a2bq=0,a3bq=0;
        #pragma unroll
        for (int k = 0; k < 12; k++) {
            ab0  += dA_ [r*12+k]*sb0[k];  a2b0 += dA2_[r*12+k]*sb0[k];  a3b0 += dA3_[r*12+k]*sb0[k];
            abq  += dA_ [r*12+k]*sBq[k];  a2bq += dA2_[r*12+k]*sBq[k];  a3bq += dA3_[r*12+k]*sBq[k];
        }
        g_ptv[r] = (float)(h/2.0*sb0[r] + h2/3.0*ab0 + h3/8.0*a2b0 + h4/24.0*a3b0);
        g_qtv[r] = (float)(h/2.0*sb0[r] + h2/6.0*ab0 + h3/24.0*a2b0);
        g_vv [r] = (float)(h*sBq[r] + h2/2.0*abq + h3/6.0*a2bq + h4/24.0*a3bq);
    }
    __syncthreads();

    // ML = M^27 = M16*M8*M2*M
    mm144(dP2_,  dM_,   dM_,   t);
    mm144(dP4_,  dP2_,  dP2_,  t);
    mm144(dP8_,  dP4_,  dP4_,  t);
    mm144(dP16_, dP8_,  dP8_,  t);
    mm144(dT1_,  dP16_, dP8_,  t);   // M^24
    mm144(dT2_,  dT1_,  dP2_,  t);   // M^26
    mm144(dML_,  dT2_,  dM_,   t);   // M^27

    // W0 = ML^37 = ML^32 * ML^4 * ML  (group transfer matrix = M^999)
    mm144(dP2_,  dML_,  dML_,  t);   // ML^2
    mm144(dP4_,  dP2_,  dP2_,  t);   // ML^4
    mm144(dP8_,  dP4_,  dP4_,  t);   // ML^8
    mm144(dP16_, dP8_,  dP8_,  t);   // ML^16
    mm144(dT1_,  dP16_, dP16_, t);   // ML^32
    mm144(dT2_,  dT1_,  dP4_,  t);   // ML^36
    mm144(dW_[0], dT2_, dML_,  t);   // ML^37
    for (int k = 1; k < 10; k++) mm144(dW_[k], dW_[k-1], dW_[k-1], t);

    if (t < 144) {
        int r = t / 12, c = t % 12, ci = c*12 + r;      // store column-major
        g_Mcol [ci] = (float)dM_ [t];
        g_MLcol[ci] = (float)dML_[t];
        #pragma unroll
        for (int k = 0; k < 10; k++) g_Wcol[k*144 + ci] = (float)dW_[k][t];
    }
}

// ---------------- fused RK4 step: x <- M x + pt*tot + qt*ton + v ----------------
__device__ __forceinline__ void stepM(float s[12], const float* __restrict__ sM,
                                      const float* __restrict__ sPt, const float* __restrict__ sQt,
                                      const float* __restrict__ sV, float tot, float ton) {
    float ns[12];
    #pragma unroll
    for (int r = 0; r < 12; r++) ns[r] = fmaf(sPt[r], tot, fmaf(sQt[r], ton, sV[r]));
    #pragma unroll
    for (int j = 0; j < 12; j++) {
        float xj = s[j];
        #pragma unroll
        for (int r = 0; r < 12; r++) ns[r] = fmaf(sM[j*12 + r], xj, ns[r]);
    }
    #pragma unroll
    for (int r = 0; r < 12; r++) s[r] = ns[r];
}

// ---------------- K1: per-chunk forcing prefix F_c ----------------
__global__ void __launch_bounds__(BLK) k_phaseB(const float* __restrict__ Tout,
                                                const float* __restrict__ x0) {
    __shared__ float sM[144], sPt[12], sQt[12], sV[12];
    __shared__ float sTo[BLK*L_CH + 1];
    int tid = threadIdx.x;
    for (int i = tid; i < 144; i += BLK) sM[i] = g_Mcol[i];
    if (tid < 12) { sPt[tid] = g_ptv[tid]; sQt[tid] = g_qtv[tid]; sV[tid] = g_vv[tid]; }
    int base = blockIdx.x * (BLK*L_CH);
    for (int i = tid; i < BLK*L_CH + 1; i += BLK) {
        int gi = base + i; if (gi > T_LEN-1) gi = T_LEN-1;
        sTo[i] = Tout[gi];
    }
    __syncthreads();

    int c = blockIdx.x * BLK + tid;
    float s[12];
    #pragma unroll
    for (int r = 0; r < 12; r++) s[r] = 0.f;
    if (c == 0) {
        #pragma unroll
        for (int r = 0; r < 12; r++) s[r] = x0[r];   // fold x0 into chunk 0
    }
    int off = tid * L_CH;
    float tot = sTo[off];
    #pragma unroll 1
    for (int i = 0; i < L_CH; i++) {
        float ton = sTo[off + i + 1];
        stepM(s, sM, sPt, sQt, sV, tot, ton);
        tot = ton;
    }
    g_F[c*3+0] = make_float4(s[0], s[1], s[2],  s[3]);
    g_F[c*3+1] = make_float4(s[4], s[5], s[6],  s[7]);
    g_F[c*3+2] = make_float4(s[8], s[9], s[10], s[11]);
}

// affine fold helper: t <- ML * t + F
__device__ __forceinline__ void affineFold(float t[12], const float4 f0, const float4 f1,
                                           const float4 f2, const float* __restrict__ sML) {
    float fv[12] = {f0.x,f0.y,f0.z,f0.w, f1.x,f1.y,f1.z,f1.w, f2.x,f2.y,f2.z,f2.w};
    float ns[12];
    #pragma unroll
    for (int r = 0; r < 12; r++) ns[r] = fv[r];
    #pragma unroll
    for (int j = 0; j < 12; j++) {
        float xj = t[j];
        #pragma unroll
        for (int r = 0; r < 12; r++) ns[r] = fmaf(sML[j*12 + r], xj, ns[r]);
    }
    #pragma unroll
    for (int r = 0; r < 12; r++) t[r] = ns[r];
}

// ---------------- K2: group aggregates H_g (fold 37 chunks with M^27) ----------------
__global__ void k_group(void) {
    __shared__ float sML[144];
    int tid = threadIdx.x;
    for (int i = tid; i < 144; i += 32) sML[i] = g_MLcol[i];
    __syncthreads();
    int g = blockIdx.x * 32 + tid;
    float t[12];
    #pragma unroll
    for (int r = 0; r < 12; r++) t[r] = 0.f;
    #pragma unroll 1
    for (int j = 0; j < GRP; j++) {
        int c = g * GRP + j;
        affineFold(t, g_F[c*3], g_F[c*3+1], g_F[c*3+2], sML);
    }
    g_H[g*3+0] = make_float4(t[0], t[1], t[2],  t[3]);
    g_H[g*3+1] = make_float4(t[4], t[5], t[6],  t[7]);
    g_H[g*3+2] = make_float4(t[8], t[9], t[10], t[11]);
}

// ---------------- K3: Kogge-Stone inclusive scan over 1024 groups ----------------
__global__ void __launch_bounds__(1024) k_scan(void) {
    __shared__ float sW[10*144];
    int g = threadIdx.x;
    for (int i = g; i < 10*144; i += 1024) sW[i] = g_Wcol[i];
    float s[12];
    {
        float4 a = g_H[g*3], b = g_H[g*3+1], c = g_H[g*3+2];
        s[0]=a.x; s[1]=a.y; s[2]=a.z; s[3]=a.w;
        s[4]=b.x; s[5]=b.y; s[6]=b.z; s[7]=b.w;
        s[8]=c.x; s[9]=c.y; s[10]=c.z; s[11]=c.w;
    }
    __syncthreads();
    float4* Pin  = g_P0;
    float4* Pout = g_P1;
    Pin[g*3+0] = make_float4(s[0],s[1],s[2],s[3]);
    Pin[g*3+1] = make_float4(s[4],s[5],s[6],s[7]);
    Pin[g*3+2] = make_float4(s[8],s[9],s[10],s[11]);
    __syncthreads();
    #pragma unroll 1
    for (int k = 0; k < 10; k++) {
        int d = 1 << k;
        if (g >= d) {
            float4 a = Pin[(g-d)*3], b = Pin[(g-d)*3+1], c = Pin[(g-d)*3+2];
            float p[12] = {a.x,a.y,a.z,a.w, b.x,b.y,b.z,b.w, c.x,c.y,c.z,c.w};
            #pragma unroll
            for (int j = 0; j < 12; j++) {
                float xj = p[j];
                #pragma unroll
                for (int r = 0; r < 12; r++) s[r] = fmaf(sW[k*144 + j*12 + r], xj, s[r]);
            }
        }
        Pout[g*3+0] = make_float4(s[0],s[1],s[2],s[3]);
        Pout[g*3+1] = make_float4(s[4],s[5],s[6],s[7]);
        Pout[g*3+2] = make_float4(s[8],s[9],s[10],s[11]);
        __syncthreads();
        float4* tmp = Pin; Pin = Pout; Pout = tmp;
    }
    g_Pf[g*3+0] = make_float4(s[0],s[1],s[2],s[3]);
    g_Pf[g*3+1] = make_float4(s[4],s[5],s[6],s[7]);
    g_Pf[g*3+2] = make_float4(s[8],s[9],s[10],s[11]);
}

// ---------------- K4: expand group prefixes to all chunk-end states G_c ----------------
__global__ void k_expand(void) {
    __shared__ float sML[144];
    int tid = threadIdx.x;
    for (int i = tid; i < 144; i += 32) sML[i] = g_MLcol[i];
    __syncthreads();
    int g = blockIdx.x * 32 + tid;
    float t[12];
    if (g == 0) {
        #pragma unroll
        for (int r = 0; r < 12; r++) t[r] = 0.f;
    } else {
        float4 a = g_Pf[(g-1)*3], b = g_Pf[(g-1)*3+1], c = g_Pf[(g-1)*3+2];
        t[0]=a.x; t[1]=a.y; t[2]=a.z; t[3]=a.w;
        t[4]=b.x; t[5]=b.y; t[6]=b.z; t[7]=b.w;
        t[8]=c.x; t[9]=c.y; t[10]=c.z; t[11]=c.w;
    }
    #pragma unroll 1
    for (int j = 0; j < GRP; j++) {
        int c = g * GRP + j;
        affineFold(t, g_F[c*3], g_F[c*3+1], g_F[c*3+2], sML);
        g_G[c*3+0] = make_float4(t[0], t[1], t[2],  t[3]);
        g_G[c*3+1] = make_float4(t[4], t[5], t[6],  t[7]);
        g_G[c*3+2] = make_float4(t[8], t[9], t[10], t[11]);
    }
}

// ---------------- K5: final pass, write all outputs ----------------
__global__ void __launch_bounds__(BLK) k_phaseD(const float* __restrict__ Tout,
                                                const float* __restrict__ x0,
                                                float4* __restrict__ out4) {
    __shared__ float sM[144], sPt[12], sQt[12], sV[12];
    __shared__ float sTo[BLK*L_CH + 1];
    int tid = threadIdx.x;
    for (int i = tid; i < 144; i += BLK) sM[i] = g_Mcol[i];
    if (tid < 12) { sPt[tid] = g_ptv[tid]; sQt[tid] = g_qtv[tid]; sV[tid] = g_vv[tid]; }
    int base = blockIdx.x * (BLK*L_CH);
    for (int i = tid; i < BLK*L_CH + 1; i += BLK) {
        int gi = base + i; if (gi > T_LEN-1) gi = T_LEN-1;
        sTo[i] = Tout[gi];
    }
    __syncthreads();

    int c = blockIdx.x * BLK + tid;
    float s[12];
    if (c == 0) {
        #pragma unroll
        for (int r = 0; r < 12; r++) s[r] = x0[r];
        out4[0] = make_float4(s[0], s[1], s[2],  s[3]);    // row 0 = x0
        out4[1] = make_float4(s[4], s[5], s[6],  s[7]);
        out4[2] = make_float4(s[8], s[9], s[10], s[11]);
    } else {
        float4 a = g_G[(c-1)*3], b = g_G[(c-1)*3+1], cc = g_G[(c-1)*3+2];
        s[0]=a.x; s[1]=a.y; s[2]=a.z; s[3]=a.w;
        s[4]=b.x; s[5]=b.y; s[6]=b.z; s[7]=b.w;
        s[8]=cc.x; s[9]=cc.y; s[10]=cc.z; s[11]=cc.w;
    }

    int n0 = c * L_CH;
    int nmax = S_LEN - n0;
    if (nmax < 0) nmax = 0;
    if (nmax > L_CH) nmax = L_CH;

    int off = tid * L_CH;
    float tot = sTo[off];
    #pragma unroll 1
    for (int i = 0; i < nmax; i++) {
        float ton = sTo[off + i + 1];
        stepM(s, sM, sPt, sQt, sV, tot, ton);
        tot = ton;
        int n1 = n0 + i + 1;
        out4[n1*3+0] = make_float4(s[0], s[1], s[2],  s[3]);
        out4[n1*3+1] = make_float4(s[4], s[5], s[6],  s[7]);
        out4[n1*3+2] = make_float4(s[8], s[9], s[10], s[11]);
    }
}

// ---------------- launch ----------------
extern "C" void kernel_launch(void* const* d_in, const int* in_sizes, int n_in,
                              void* d_out, int out_size) {
    const float* t_eval = (const float*)d_in[0];
    const float* x0     = (const float*)d_in[1];
    const float* A      = (const float*)d_in[2];
    const float* B      = (const float*)d_in[3];
    const float* Tout   = (const float*)d_in[4];
    const float* loads  = (const float*)d_in[5];
    const float* areas  = (const float*)d_in[6];
    float4* out4 = (float4*)d_out;

    k_setup <<<1,    256>>>(t_eval, A, B, loads, areas);
    k_phaseB<<<NBLK, BLK>>>(Tout, x0);
    k_group <<<32,   32 >>>();
    k_scan  <<<1,    1024>>>();
    k_expand<<<32,   32 >>>();
    k_phaseD<<<NBLK, BLK>>>(Tout, x0, out4);
}

// round 3
// speedup vs baseline: 1.3450x; 1.3450x over previous
#include <cuda_runtime.h>
#include <math.h>

#define T_LEN   1000000
#define S_LEN    999999          // RK4 steps
#define LCH      31              // steps per chunk
#define C1       32768           // chunks (= 2^15), 128 blocks x 256 threads
#define NB1      128
#define BLK      256

// ---------------- scratch (__device__ globals) ----------------
__device__ float4 g_PW [C1*3];       // within-warp inclusive chunk prefixes
__device__ float4 g_A  [1024*3];     // warp aggregates
__device__ float4 g_PW2[1024*3];     // within-block-of-warps prefixes
__device__ float4 g_A2 [32*3];       // block aggregates
__device__ float4 g_GP3[32*3];       // inclusive block prefixes

__device__ float g_Mcol[144];        // M column-major
__device__ float g_ptv[12], g_qtv[12], g_vv[12];
__device__ float g_U[32*12];         // conv coefficients, col i at [i*12..]
__device__ float g_vc[12];
__device__ float g_TabAcol[32*144];  // M^(31*j), j=1..32 at slot (j-1), col-major
__device__ float g_TabBcol[32*144];  // M^(992*j), j=1..32, col-major
__device__ float g_SCcol[5*144];     // M^(31744*2^k), k=0..4, col-major

// matrix power pool (row-major fp32): [0..31]=M^j, [32..63]=M^(31j) j=1..32,
// [64..95]=M^(992j) j=1..32, [96..100]=M^(31744*2^k) k=0..4
__device__ float fPool[101][144];

// fp64 setup scratch
__device__ double dA_[144], dA2_[144], dA3_[144], dA4_[144], dMm_[144];
__device__ double dpv_[12], dqv_[12], dvv_[12];

// product triples (dst, a, b) into fPool; grouped into rounds (sources always
// from earlier rounds -> batchable within a round)
__device__ const unsigned char tripD[99] = {
    2, 3,4, 5,6,7,8, 9,10,11,12,13,14,15,16,
    17,18,19,20,21,22,23,24,25,26,27,28,29,30,31,
    32, 33, 34,35, 36,37,38,39, 40,41,42,43,44,45,46,47,
    48,49,50,51,52,53,54,55,56,57,58,59,60,61,62,63,
    64, 65, 66,67, 68,69,70,71, 72,73,74,75,76,77,78,79,
    80,81,82,83,84,85,86,87,88,89,90,91,92,93,94,95,
    96, 97, 98, 99, 100 };
__device__ const unsigned char tripA[99] = {
    1, 2,2, 4,4,4,4, 8,8,8,8,8,8,8,8,
    16,16,16,16,16,16,16,16,16,16,16,16,16,16,16,
    31, 32, 33,33, 35,35,35,35, 39,39,39,39,39,39,39,39,
    47,47,47,47,47,47,47,47,47,47,47,47,47,47,47,47,
    63, 64, 65,65, 67,67,67,67, 71,71,71,71,71,71,71,71,
    79,79,79,79,79,79,79,79,79,79,79,79,79,79,79,79,
    95, 96, 97, 98, 99 };
__device__ const unsigned char tripB[99] = {
    1, 1,2, 1,2,3,4, 1,2,3,4,5,6,7,8,
    1,2,3,4,5,6,7,8,9,10,11,12,13,14,15,
    0, 32, 32,33, 32,33,34,35, 32,33,34,35,36,37,38,39,
    32,33,34,35,36,37,38,39,40,41,42,43,44,45,46,47,
    0, 64, 64,65, 64,65,66,67, 64,65,66,67,68,69,70,71,
    64,65,66,67,68,69,70,71,72,73,74,75,76,77,78,79,
    0, 96, 97, 98, 99 };
__device__ const short rndOff[23] = {0,1,3,7,15,30,31,32,34,38,46,62,63,64,66,70,78,94,95,96,97,98,99};

// ---------------- K0: setup ----------------
__global__ void __launch_bounds__(1024) k_setup(const float* __restrict__ t_eval,
                                                const float* __restrict__ A,
                                                const float* __restrict__ B,
                                                const float* __restrict__ loads_raw,
                                                const float* __restrict__ room_areas) {
    __shared__ double sQw[10], sb0[12], sBq[12], sh;
    __shared__ float sTsum[144];
    int t = threadIdx.x;

    if (t == 0) sh = (double)t_eval[1] - (double)t_eval[0];
    if (t < 10) {
        double x = (double)loads_raw[10 + t];    // gain row (action = 0)
        sQw[t] = 1.0 / (1.0 + exp(-x)) * 50.0 * (double)room_areas[t];
    }
    if (t < 144) dA_[t] = (double)A[t];
    __syncthreads();
    if (t < 12) {
        sb0[t] = (double)B[t*11];
        double s = 0.0;
        #pragma unroll
        for (int j = 0; j < 10; j++) s += (double)B[t*11 + 1 + j] * sQw[j];
        sBq[t] = s;
    }
    __syncthreads();

    // fp64 A powers
    if (t < 144) { int r=t/12,c=t%12; double s=0;
        #pragma unroll
        for(int j=0;j<12;j++) s += dA_[r*12+j]*dA_[j*12+c]; dA2_[t]=s; }
    __syncthreads();
    if (t < 144) { int r=t/12,c=t%12; double s=0;
        #pragma unroll
        for(int j=0;j<12;j++) s += dA2_[r*12+j]*dA_[j*12+c]; dA3_[t]=s; }
    __syncthreads();
    if (t < 144) { int r=t/12,c=t%12; double s=0;
        #pragma unroll
        for(int j=0;j<12;j++) s += dA2_[r*12+j]*dA2_[j*12+c]; dA4_[t]=s; }
    __syncthreads();

    double h = sh, h2 = h*h, h3 = h2*h, h4 = h3*h;
    if (t < 144) {
        int r = t/12, c = t%12;
        double m = (r==c?1.0:0.0) + h*dA_[t] + h2/2.0*dA2_[t] + h3/6.0*dA3_[t] + h4/24.0*dA4_[t];
        dMm_[t] = m;
        fPool[1][t] = (float)m;
        fPool[0][t] = (r==c) ? 1.0f : 0.0f;
        g_Mcol[c*12 + r] = (float)m;
    }
    if (t < 12) {
        int r = t;
        double ab0=0,a2b0=0,a3b0=0,abq=0,a2bq=0,a3bq=0;
        #pragma unroll
        for (int k = 0; k < 12; k++) {
            ab0 += dA_ [r*12+k]*sb0[k]; a2b0 += dA2_[r*12+k]*sb0[k]; a3b0 += dA3_[r*12+k]*sb0[k];
            abq += dA_ [r*12+k]*sBq[k]; a2bq += dA2_[r*12+k]*sBq[k]; a3bq += dA3_[r*12+k]*sBq[k];
        }
        double pt = h/2.0*sb0[r] + h2/3.0*ab0 + h3/8.0*a2b0 + h4/24.0*a3b0;
        double qt = h/2.0*sb0[r] + h2/6.0*ab0 + h3/24.0*a2b0;
        double vv = h*sBq[r] + h2/2.0*abq + h3/6.0*a2bq + h4/24.0*a3bq;
        dpv_[r]=pt; dqv_[r]=qt; dvv_[r]=vv;
        g_ptv[r]=(float)pt; g_qtv[r]=(float)qt; g_vv[r]=(float)vv;
    }
    __syncthreads();

    // fp32 power-pool via batched doubling (7 products per pass, 144 thr each)
    for (int rd = 0; rd < 22; rd++) {
        int s0 = rndOff[rd], s1 = rndOff[rd+1];
        for (int base = s0; base < s1; base += 7) {
            int pid = t / 144, e = t % 144;
            int k = base + pid;
            bool act = (pid < 7) && (k < s1);
            float acc = 0.f;
            if (act) {
                const float* a = fPool[tripA[k]];
                const float* b = fPool[tripB[k]];
                int r = e/12, c = e%12;
                #pragma unroll
                for (int j = 0; j < 12; j++) acc = fmaf(a[r*12+j], b[j*12+c], acc);
            }
            __syncthreads();
            if (act) fPool[tripD[k]][e] = acc;
            __syncthreads();
        }
    }

    // conv coefficients: u_i = M^(30-i) p  (i<=30)  +  M^(31-i) q  (i>=1)
    if (t < 384) {
        int i = t / 12, r = t % 12;
        double s = 0.0;
        if (i <= 30) {
            const float* m = fPool[30 - i];
            #pragma unroll
            for (int j = 0; j < 12; j++) s += (double)m[r*12+j] * dpv_[j];
        }
        if (i >= 1) {
            const float* m = fPool[31 - i];
            #pragma unroll
            for (int j = 0; j < 12; j++) s += (double)m[r*12+j] * dqv_[j];
        }
        g_U[i*12 + r] = (float)s;
    }
    // vc = (sum_{j=0}^{30} M^j) v
    if (t < 144) {
        float s = 0.f;
        for (int j = 0; j <= 30; j++) s += fPool[j][t];
        sTsum[t] = s;
    }
    __syncthreads();
    if (t < 12) {
        double s = 0.0;
        #pragma unroll
        for (int k = 0; k < 12; k++) s += (double)sTsum[t*12 + k] * dvv_[k];
        g_vc[t] = (float)s;
    }

    // col-major table exports
    for (int idx = t; idx < 32*144; idx += 1024) {
        int j = idx / 144, e = idx % 144, r = e/12, c = e%12;
        g_TabAcol[j*144 + c*12 + r] = fPool[32 + j][e];
        g_TabBcol[j*144 + c*12 + r] = fPool[64 + j][e];
    }
    for (int idx = t; idx < 5*144; idx += 1024) {
        int j = idx / 144, e = idx % 144, r = e/12, c = e%12;
        g_SCcol[j*144 + c*12 + r] = fPool[96 + j][e];
    }
}

// ---------------- helpers ----------------
__device__ __forceinline__ void ld12(float* s, const float4* p) {
    float4 a = p[0], b = p[1], c = p[2];
    s[0]=a.x; s[1]=a.y; s[2]=a.z; s[3]=a.w;
    s[4]=b.x; s[5]=b.y; s[6]=b.z; s[7]=b.w;
    s[8]=c.x; s[9]=c.y; s[10]=c.z; s[11]=c.w;
}
__device__ __forceinline__ void st12(float4* p, const float* s) {
    p[0] = make_float4(s[0],s[1],s[2],s[3]);
    p[1] = make_float4(s[4],s[5],s[6],s[7]);
    p[2] = make_float4(s[8],s[9],s[10],s[11]);
}
// s += Mcol * o   (column-major matrix)
__device__ __forceinline__ void mv_acc(float* s, const float* M, const float* o) {
    #pragma unroll
    for (int j = 0; j < 12; j++) {
        float oj = o[j];
        #pragma unroll
        for (int r = 0; r < 12; r++) s[r] = fmaf(M[j*12+r], oj, s[r]);
    }
}
// warp-level inclusive affine scan, 5 rounds, matrices in sMat[k*144..]
__device__ __forceinline__ void warpscan12(float* s, const float* sMat, int lane) {
    #pragma unroll
    for (int k = 0; k < 5; k++) {
        int d = 1 << k;
        float o[12];
        #pragma unroll
        for (int r = 0; r < 12; r++) o[r] = __shfl_up_sync(0xffffffffu, s[r], d);
        if (lane >= d) mv_acc(s, sMat + k*144, o);
    }
}

// ---------------- K1: conv forcing prefix + warp scan ----------------
__global__ void __launch_bounds__(BLK) k_phaseB(const float* __restrict__ Tout,
                                                const float* __restrict__ x0) {
    __shared__ float sU[384], sVc[12], sSA[5*144];
    __shared__ float sTo[BLK*LCH + 1];
    int tid = threadIdx.x;
    for (int i = tid; i < 384; i += BLK) sU[i] = g_U[i];
    if (tid < 12) sVc[tid] = g_vc[tid];
    for (int i = tid; i < 5*144; i += BLK) {
        int k = i / 144, e = i % 144;
        sSA[i] = g_TabAcol[((1<<k) - 1)*144 + e];
    }
    int base = blockIdx.x * (BLK*LCH);
    for (int i = tid; i < BLK*LCH + 1; i += BLK) {
        int g = base + i; if (g > T_LEN-1) g = T_LEN-1;
        sTo[i] = Tout[g];
    }
    __syncthreads();

    int c = blockIdx.x * BLK + tid;
    int lane = tid & 31;
    float s[12];
    #pragma unroll
    for (int r = 0; r < 12; r++) s[r] = sVc[r];
    int off = tid * LCH;
    #pragma unroll
    for (int i = 0; i < 32; i++) {
        float to = sTo[off + i];
        #pragma unroll
        for (int r = 0; r < 12; r++) s[r] = fmaf(sU[i*12+r], to, s[r]);
    }
    if (c == 0) {        // fold M^L * x0 into chunk 0
        float xv[12];
        #pragma unroll
        for (int r = 0; r < 12; r++) xv[r] = x0[r];
        mv_acc(s, sSA, xv);    // sSA[0..143] = M^31 col-major
    }

    warpscan12(s, sSA, lane);

    st12(&g_PW[c*3], s);
    if (lane == 31) st12(&g_A[(c >> 5)*3], s);
}

// ---------------- K2: scan 1024 warp aggregates (32 blocks x 32 lanes) ----------------
__global__ void k_scan2(void) {
    __shared__ float sSB[5*144];
    int lane = threadIdx.x;
    for (int i = lane; i < 5*144; i += 32) {
        int k = i / 144, e = i % 144;
        sSB[i] = g_TabBcol[((1<<k) - 1)*144 + e];
    }
    __syncthreads();
    int w = blockIdx.x * 32 + lane;
    float s[12];
    ld12(s, &g_A[w*3]);
    warpscan12(s, sSB, lane);
    st12(&g_PW2[w*3], s);
    if (lane == 31) st12(&g_A2[blockIdx.x*3], s);
}

// ---------------- K3: scan 32 block aggregates (1 warp) ----------------
__global__ void k_scan3(void) {
    __shared__ float sSC[5*144];
    int lane = threadIdx.x;
    for (int i = lane; i < 5*144; i += 32) sSC[i] = g_SCcol[i];
    __syncthreads();
    float s[12];
    ld12(s, &g_A2[lane*3]);
    warpscan12(s, sSC, lane);
    st12(&g_GP3[lane*3], s);
}

// ---------------- fused RK4 step: x <- M x + pt*tot + qt*ton + v ----------------
__device__ __forceinline__ void stepM(float s[12], const float* __restrict__ sM,
                                      const float* __restrict__ sPt, const float* __restrict__ sQt,
                                      const float* __restrict__ sV, float tot, float ton) {
    float ns[12];
    #pragma unroll
    for (int r = 0; r < 12; r++) ns[r] = fmaf(sPt[r], tot, fmaf(sQt[r], ton, sV[r]));
    #pragma unroll
    for (int j = 0; j < 12; j++) {
        float xj = s[j];
        #pragma unroll
        for (int r = 0; r < 12; r++) ns[r] = fmaf(sM[j*12+r], xj, ns[r]);
    }
    #pragma unroll
    for (int r = 0; r < 12; r++) s[r] = ns[r];
}

// ---------------- K4: final pass, write all outputs ----------------
__global__ void __launch_bounds__(BLK) k_phaseD(const float* __restrict__ Tout,
                                                const float* __restrict__ x0,
                                                float4* __restrict__ out4) {
    __shared__ float sM[144], sPt[12], sQt[12], sV[12];
    __shared__ float sTo[BLK*LCH + 1];
    int tid = threadIdx.x;
    for (int i = tid; i < 144; i += BLK) sM[i] = g_Mcol[i];
    if (tid < 12) { sPt[tid]=g_ptv[tid]; sQt[tid]=g_qtv[tid]; sV[tid]=g_vv[tid]; }
    int base = blockIdx.x * (BLK*LCH);
    for (int i = tid; i < BLK*LCH + 1; i += BLK) {
        int g = base + i; if (g > T_LEN-1) g = T_LEN-1;
        sTo[i] = Tout[g];
    }
    __syncthreads();

    int c = blockIdx.x * BLK + tid;
    float s[12];
    if (c == 0) {
        #pragma unroll
        for (int r = 0; r < 12; r++) s[r] = x0[r];
        out4[0] = make_float4(s[0],s[1],s[2],s[3]);
        out4[1] = make_float4(s[4],s[5],s[6],s[7]);
        out4[2] = make_float4(s[8],s[9],s[10],s[11]);
    } else {
        int cm1 = c - 1, r1 = cm1 & 31, w = cm1 >> 5;
        ld12(s, &g_PW[cm1*3]);
        if (w >= 1) {
            int wm1 = w - 1, q = wm1 & 31, b = wm1 >> 5;
            float tv[12];
            ld12(tv, &g_PW2[wm1*3]);
            if (b >= 1) {
                float gv[12];
                ld12(gv, &g_GP3[(b-1)*3]);
                mv_acc(tv, g_TabBcol + q*144, gv);
            }
            mv_acc(s, g_TabAcol + r1*144, tv);
        }
    }

    int n0 = c * LCH;
    int nmax = S_LEN - n0;
    if (nmax < 0) nmax = 0;
    if (nmax > LCH) nmax = LCH;

    int off = tid * LCH;
    float tot = sTo[off];
    #pragma unroll 1
    for (int i = 0; i < nmax; i++) {
        float ton = sTo[off + i + 1];
        stepM(s, sM, sPt, sQt, sV, tot, ton);
        tot = ton;
        int n1 = n0 + i + 1;
        out4[n1*3+0] = make_float4(s[0],s[1],s[2],s[3]);
        out4[n1*3+1] = make_float4(s[4],s[5],s[6],s[7]);
        out4[n1*3+2] = make_float4(s[8],s[9],s[10],s[11]);
    }
}

// ---------------- launch ----------------
extern "C" void kernel_launch(void* const* d_in, const int* in_sizes, int n_in,
                              void* d_out, int out_size) {
    const float* t_eval = (const float*)d_in[0];
    const float* x0     = (const float*)d_in[1];
    const float* A      = (const float*)d_in[2];
    const float* B      = (const float*)d_in[3];
    const float* Tout   = (const float*)d_in[4];
    const float* loads  = (const float*)d_in[5];
    const float* areas  = (const float*)d_in[6];
    float4* out4 = (float4*)d_out;

    k_setup <<<1,    1024>>>(t_eval, A, B, loads, areas);
    k_phaseB<<<NB1,  BLK>>>(Tout, x0);
    k_scan2 <<<32,   32>>>();
    k_scan3 <<<1,    32>>>();
    k_phaseD<<<NB1,  BLK>>>(Tout, x0, out4);
}